// round 16
// baseline (speedup 1.0000x reference)
#include <cuda_runtime.h>
#include <cuda_fp16.h>
#include <math.h>
#include <stdint.h>

#define BATCH 1024
#define INF   256
#define OUTF  256
#define NBF   9
#define KD    2304          // NBF * INF; k = n*INF + i
#define NSPLIT 8
#define BK    64            // k elems per mainloop iter (36 tiles total)
#define BM 128
#define BN 64
#define NSTAGE 3

// ---- scratch (__device__ globals: allocation-free rule) ----
__device__ __half g_F[(size_t)BATCH * KD];
__device__ __half g_W[(size_t)OUTF * KD];

// ---------------------------------------------------------------------------
// prep_all: ONE launch does everything before the GEMM.
//   blocks [0,1024)      : prep_f (closed-form B-spline scatter, 1 CTA/row)
//   blocks [1024,1152)   : prep_w
//   blocks [1152,1408)   : zero out[] (65536 float4, exactly 1 per thread)
// ---------------------------------------------------------------------------
__global__ __launch_bounds__(256, 8)
void prep_all_kernel(const float* __restrict__ x,
                     const float* __restrict__ grid,
                     const float* __restrict__ coeff,
                     const float* __restrict__ base_weight,
                     const float* __restrict__ spline_weight,
                     float* __restrict__ out) {
    const int blk = blockIdx.x;
    const int tid = threadIdx.x;

    if (blk < BATCH) {
        // ---------------- prep_f: closed-form cubic B-spline + silu --------
        __shared__ float s[NBF][INF + 4];
        const int b = blk, i = tid;
        const float v  = x[b * INF + i];
        const float g0 = __ldg(grid + 0);
        const float g8 = __ldg(grid + 8);
        const float c16 = 1.0f / 6.0f;

#pragma unroll
        for (int n = 0; n < NBF; n++) s[n][i] = 0.0f;

        float tp = (v - g0) * 2.5f;       // 1/h, h = 0.4
        float jf = floorf(tp);
        float u  = tp - jf;
        int   j  = (int)jf;
        if (j >= 0 && j <= 10) {
            float u2 = u * u, u3 = u2 * u, omu = 1.0f - u;
            float w0 = omu * omu * omu * c16;
            float w1 = fmaf(3.0f, u3, fmaf(-6.0f, u2, 4.0f)) * c16;
            float w2 = fmaf(-3.0f, u3, fmaf(3.0f, u2, fmaf(3.0f, u, 1.0f))) * c16;
            float w3 = u3 * c16;
            if (j     <= 7)               s[j    ][i] = w3;
            if (j - 1 >= 0 && j - 1 <= 7) s[j - 1][i] = w2;
            if (j - 2 >= 0 && j - 2 <= 7) s[j - 2][i] = w1;
            if (j - 3 >= 0)               s[j - 3][i] = w0;
        }
        if (v >= g8) s[7][i] += 1.0f;     // reference tail
        s[8][i] = __fdividef(v, 1.0f + __expf(-v));   // silu
        __syncthreads();

        size_t rowb = (size_t)b * KD;
        for (int slot = i; slot < 576; slot += 256) {
            int n = slot >> 6, c = slot & 63;
            float4 f = *(const float4*)&s[n][c * 4];
            __half2 h0 = __floats2half2_rn(f.x, f.y);
            __half2 h1 = __floats2half2_rn(f.z, f.w);
            uint2 hp;
            hp.x = *(uint32_t*)&h0; hp.y = *(uint32_t*)&h1;
            *(uint2*)&g_F[rowb + n * INF + c * 4] = hp;
        }
    } else if (blk < BATCH + 128) {
        // ---------------- prep_w -------------------------------------------
        int t = (blk - BATCH) * 256 + tid;            // 0 .. 32767
        int o  = t >> 7;
        int i2 = (t & 127) * 2;
        float2 s2 = ((const float2*)spline_weight)[t];
        float2 bw = ((const float2*)base_weight)[t];
        const float4* c4 = (const float4*)(coeff + ((size_t)o * INF + i2) * 8);
        float4 a0 = c4[0], a1 = c4[1], a2 = c4[2], a3 = c4[3];
        float cv[2][9] = {
            {a0.x * s2.x, a0.y * s2.x, a0.z * s2.x, a0.w * s2.x,
             a1.x * s2.x, a1.y * s2.x, a1.z * s2.x, a1.w * s2.x, bw.x},
            {a2.x * s2.y, a2.y * s2.y, a2.z * s2.y, a2.w * s2.y,
             a3.x * s2.y, a3.y * s2.y, a3.z * s2.y, a3.w * s2.y, bw.y}};
        size_t rowb = (size_t)o * KD + i2;
#pragma unroll
        for (int n = 0; n < 9; n++) {
            __half2 hv = __floats2half2_rn(cv[0][n], cv[1][n]);
            *(__half2*)&g_W[rowb + n * INF] = hv;
        }
    } else {
        // ---------------- zero out[]: 256 CTAs x 256 thr x 1 float4 -------
        int slot = (blk - BATCH - 128) * 256 + tid;   // 0 .. 65535 (all slots)
        ((float4*)out)[slot] = make_float4(0.f, 0.f, 0.f, 0.f);
    }
}

// ---------------------------------------------------------------------------
// GEMM: out += F * W^T (fp16 in / fp32 accum), K = 2304, split-K z=8,
// BK=64 (36 K-tiles; z<4 take 5 tiles, z>=4 take 4 -> fewer, fatter iters:
// half the syncs/waits of BK=32). mma.sync m16n8k16, BM=128 BN=64, 8 warps,
// 3-stage cp.async ring in 72KB DYNAMIC smem (occ 2: 144KB < 228KB).
// Full-128B-row XOR swizzle (c ^ (row&7)). grid (8,4,8) = 256 CTAs.
// Epilogue: restage tile in smem, then red.global.add.v4.f32 into out.
// ---------------------------------------------------------------------------
#define A_TILE_B (BM * 128)     // 16384 (128 rows x 128B)
#define B_TILE_B (BN * 128)     // 8192
#define STAGE_B  (A_TILE_B + B_TILE_B)      // 24576
#define SMEM_BYTES (NSTAGE * STAGE_B)       // 73728

#define CP16(dst_u32, src_ptr) \
    asm volatile("cp.async.cg.shared.global [%0], [%1], 16;\n" \
                 :: "r"(dst_u32), "l"(src_ptr))

#define LDMX4(r0,r1,r2,r3, addr) \
    asm volatile("ldmatrix.sync.aligned.m8n8.x4.shared.b16 {%0,%1,%2,%3}, [%4];\n" \
                 : "=r"(r0),"=r"(r1),"=r"(r2),"=r"(r3) : "r"(addr))

#define MMA_F16(d, a, b0_, b1_) \
    asm volatile("mma.sync.aligned.m16n8k16.row.col.f32.f16.f16.f32 " \
                 "{%0,%1,%2,%3},{%4,%5,%6,%7},{%8,%9},{%0,%1,%2,%3};\n" \
                 : "+f"(d[0]),"+f"(d[1]),"+f"(d[2]),"+f"(d[3]) \
                 : "r"(a[0]),"r"(a[1]),"r"(a[2]),"r"(a[3]),"r"(b0_),"r"(b1_))

#define REDV4(ptr, v) \
    asm volatile("red.global.add.v4.f32 [%0], {%1, %2, %3, %4};\n" \
                 :: "l"(ptr), "f"((v).x), "f"((v).y), "f"((v).z), "f"((v).w) \
                 : "memory")

// swizzled 16B-chunk offset within a tile: row has 8 chunks of 16B
#define SWZ(row, c) ((uint32_t)((((row) * 8) + ((c) ^ ((row) & 7))) << 4))

__global__ __launch_bounds__(256, 2)
void gemm_kernel(float* __restrict__ out) {
    extern __shared__ __align__(16) uint8_t smem[];

    const int tid  = threadIdx.x;
    const int warp = tid >> 5;
    const int lane = tid & 31;
    const int bm = blockIdx.x * BM;
    const int bn = blockIdx.y * BN;
    const int z  = blockIdx.z;
    const int wm = (warp >> 1) * 32;    // 0,32,64,96
    const int wn = (warp & 1) * 32;     // 0,32

    const uint32_t smem_u32 = (uint32_t)__cvta_generic_to_shared(smem);

    // uneven K split: 36 tiles, z<4 get 5, z>=4 get 4
    const int it0 = z * 4 + (z < 4 ? z : 4);
    const int IT  = 4 + (z < 4 ? 1 : 0);

    auto load_tile = [&](int stage, int it) {
        int k0 = it * BK;
        uint32_t sA = smem_u32 + stage * STAGE_B;
        uint32_t sB = sA + A_TILE_B;
#pragma unroll
        for (int h = 0; h < 4; h++) {           // A: 1024 16B chunks
            int slot = tid + h * 256;
            int row = slot >> 3, c = slot & 7;
            const __half* gp = g_F + (size_t)(bm + row) * KD + k0 + c * 8;
            CP16(sA + SWZ(row, c), gp);
        }
#pragma unroll
        for (int h = 0; h < 2; h++) {           // B: 512 chunks
            int slot = tid + h * 256;
            int row = slot >> 3, c = slot & 7;
            const __half* gp = g_W + (size_t)(bn + row) * KD + k0 + c * 8;
            CP16(sB + SWZ(row, c), gp);
        }
        asm volatile("cp.async.commit_group;\n" ::);
    };

    float acc[2][4][4];
#pragma unroll
    for (int a = 0; a < 2; a++)
#pragma unroll
        for (int b = 0; b < 4; b++)
#pragma unroll
            for (int c = 0; c < 4; c++) acc[a][b][c] = 0.0f;

    load_tile(0, it0);
    load_tile(1, it0 + 1);

    for (int t = 0; t < IT; t++) {
        int nx = t + NSTAGE - 1;
        if (nx < IT) load_tile((t + 2) % NSTAGE, it0 + nx);
        else asm volatile("cp.async.commit_group;\n" ::);
        asm volatile("cp.async.wait_group 2;\n" ::);
        __syncthreads();

        int stage = t % NSTAGE;
        uint32_t aBase = smem_u32 + stage * STAGE_B;
        uint32_t bBase = aBase + A_TILE_B;

#pragma unroll
        for (int kk = 0; kk < 4; kk++) {        // 4 x k16 per BK=64 slab
            uint32_t afr[2][4];
#pragma unroll
            for (int mt = 0; mt < 2; mt++) {
                int row = wm + mt * 16 + (lane & 15);
                int ch  = kk * 2 + (lane >> 4);
                LDMX4(afr[mt][0], afr[mt][1], afr[mt][2], afr[mt][3],
                      aBase + SWZ(row, ch));
            }
            uint32_t bfr[2][4];
#pragma unroll
            for (int nh = 0; nh < 2; nh++) {
                int row = wn + nh * 16 + ((lane >> 4) << 3) + (lane & 7);
                int ch  = kk * 2 + ((lane >> 3) & 1);
                LDMX4(bfr[nh][0], bfr[nh][1], bfr[nh][2], bfr[nh][3],
                      bBase + SWZ(row, ch));
            }
#pragma unroll
            for (int mt = 0; mt < 2; mt++)
#pragma unroll
                for (int nt = 0; nt < 4; nt++) {
                    uint32_t b0 = bfr[nt >> 1][(nt & 1) * 2];
                    uint32_t b1 = bfr[nt >> 1][(nt & 1) * 2 + 1];
                    MMA_F16(acc[mt][nt], afr[mt], b0, b1);
                }
        }
        __syncthreads();
    }

    // ---- epilogue: restage tile in smem (pipeline buffers dead) ----------
    float* accS = (float*)smem;
    const int g2 = lane >> 2, tg = lane & 3;
#pragma unroll
    for (int mt = 0; mt < 2; mt++)
#pragma unroll
        for (int nt = 0; nt < 4; nt++) {
            int r  = wm + mt * 16 + g2;
            int cc = wn + nt * 8 + tg * 2;
            *(float2*)&accS[r * BN + cc] =
                make_float2(acc[mt][nt][0], acc[mt][nt][1]);
            *(float2*)&accS[(r + 8) * BN + cc] =
                make_float2(acc[mt][nt][2], acc[mt][nt][3]);
        }
    __syncthreads();

    // ---- vector-RED accumulate into out (pre-zeroed) ---------------------
#pragma unroll
    for (int j = 0; j < (BM * BN / 4) / 256; j++) {   // 8 float4 per thread
        int slot = tid + j * 256;
        int r    = slot >> 4;                 // 0..127
        int c4   = slot & 15;                 // 0..15
        float4 v = *(const float4*)&accS[r * BN + c4 * 4];
        float* dst = &out[(size_t)(bm + r) * OUTF + bn + c4 * 4];
        REDV4(dst, v);
    }
}

// ---------------------------------------------------------------------------
extern "C" void kernel_launch(void* const* d_in, const int* in_sizes, int n_in,
                              void* d_out, int out_size) {
    const float* x             = (const float*)d_in[0];
    const float* grid          = (const float*)d_in[1];
    const float* coeff         = (const float*)d_in[2];
    const float* base_weight   = (const float*)d_in[3];
    const float* spline_weight = (const float*)d_in[4];
    float* out = (float*)d_out;

    cudaFuncSetAttribute(gemm_kernel,
                         cudaFuncAttributeMaxDynamicSharedMemorySize, SMEM_BYTES);

    prep_all_kernel<<<BATCH + 128 + 256, 256>>>(x, grid, coeff, base_weight,
                                                spline_weight, out);

    dim3 g(BATCH / BM, OUTF / BN, NSPLIT);
    gemm_kernel<<<g, 256, SMEM_BYTES>>>(out);
}